// round 11
// baseline (speedup 1.0000x reference)
#include <cuda_runtime.h>
#include <math.h>

#define BB 64
#define TT 1024
#define CC 512
#define TIE_W 1e-3f   // covers fp32 ulp of |score|<6400 (<=4.88e-4) + lp rounding

// device scratch (allocation-free per harness rules)
__device__ float2 g_m[BB * TT];    // .x = lp1 (= -L), .y = int bits: cls | (tie?1<<30)
__device__ int    g_cnt[BB];       // arrival counters (zero-init; self-resetting)

// order-preserving float -> uint key (and inverse)
__device__ __forceinline__ unsigned fkey(float f) {
    unsigned b = __float_as_uint(f);
    return b ^ ((unsigned)((int)b >> 31) | 0x80000000u);
}
__device__ __forceinline__ float unkey(unsigned k) {
    unsigned b = (k & 0x80000000u) ? (k ^ 0x80000000u) : ~k;
    return __uint_as_float(b);
}

// ---------------------------------------------------------------------------
// Fused kernel, 8192 blocks x 256 threads, HARD-BOUNDED to 42 regs (6 blk/SM):
//  Phase A (every block): one warp per (b,t) row — byte-identical arithmetic
//    to the proven split kernel (L bits must not change).
//  Election: 128th arriving block of each batch runs Phase B inline (never
//    spins — it is by definition last).
//  Phase B: round-10 decode (pure-FADD chain w/ boundary prefixes, overlapped
//    tie recompute, parallel 3-pass CTC collapse).
// ---------------------------------------------------------------------------
__global__ __launch_bounds__(256, 6) void fused_kernel(const float* __restrict__ logits,
                                                       float* __restrict__ out_f,
                                                       int* __restrict__ out_i,
                                                       int mode) {
    int tid  = threadIdx.x;
    int lane = tid & 31;
    int warp = tid >> 5;
    int gwarp = blockIdx.x * 8 + warp;   // row id = b*TT + t
    int b = blockIdx.x >> 7;             // 128 blocks per batch

    // ================= Phase A =================
    {
        const float4* row = reinterpret_cast<const float4*>(logits + (size_t)gwarp * CC);
        float x[16];
#pragma unroll
        for (int i = 0; i < 4; i++) {
            float4 v = __ldcs(row + lane + 32 * i);  // streaming, coalesced
            x[4*i+0] = v.x; x[4*i+1] = v.y; x[4*i+2] = v.z; x[4*i+3] = v.w;
        }

        float m = x[0];
#pragma unroll
        for (int k = 1; k < 16; k++) m = fmaxf(m, x[k]);
        float M = unkey(__reduce_max_sync(0xffffffffu, fkey(m)));

        int cand = 0x7fffffff;
#pragma unroll
        for (int i = 3; i >= 0; i--)
#pragma unroll
            for (int j = 3; j >= 0; j--) {
                if (x[4*i+j] == M) cand = 128*i + 4*lane + j;  // ends at smallest match
            }
        int c1 = (int)__reduce_min_sync(0xffffffffu, (unsigned)cand);

        // compensated fp32 sum of exp(x-M)  [bit-identical L — NEVER touch]
        float s = 0.0f, c = 0.0f;
#pragma unroll
        for (int k = 0; k < 16; k++) {
            float y = __expf(x[k] - M) - c;
            float t = s + y;
            c = (t - s) - y;
            s = t;
        }
        c = -c;
#pragma unroll
        for (int off = 16; off > 0; off >>= 1) {
            float os = __shfl_xor_sync(0xffffffffu, s, off);
            float oc = __shfl_xor_sync(0xffffffffu, c, off);
            float t = s + os;
            float z = t - s;
            float e = (s - (t - z)) + (os - z);
            c = c + oc + e;
            s = t;
        }
        float L = logf(s) + c / s;

        float thr = M - TIE_W;
        int cnt = 0;
#pragma unroll
        for (int k = 0; k < 16; k++) cnt += (x[k] >= thr);
        cnt = (int)__reduce_add_sync(0xffffffffu, (unsigned)cnt);

        if (lane == 0)
            g_m[gwarp] = make_float2(-L, __int_as_float(cnt < 2 ? c1 : (c1 | (1 << 30))));
    }

    // ================= last-block election =================
    __shared__ int s_last;
    __syncthreads();
    if (tid == 0) {
        __threadfence();                          // publish g_m
        int old = atomicAdd(&g_cnt[b], 1);
        s_last = (old == 127);
        if (old == 127) g_cnt[b] = 0;             // self-reset for graph replay
    }
    __syncthreads();
    if (!s_last) return;
    __threadfence();                              // acquire peers' g_m writes

    // ================= Phase B: decode batch b =================
    unsigned lmask = (lane == 0) ? 0u : (0xffffffffu >> (32 - lane));

    __shared__ __align__(16) float s_lp[TT];
    __shared__ int      s_cls[TT];
    __shared__ float    s_pref32[TT / 32];       // prefix at each 32-boundary
    __shared__ unsigned s_keepm[TT / 32];
    __shared__ int    s_tiet[64];                // flagged positions (rare)
    __shared__ float4 s_tlp[64];                 // recomputed lp1..lp3 (.x unused)
    __shared__ int4   s_tc4[64];                 // recomputed classes
    __shared__ int s_ntie;
    __shared__ int s_segFirst[8], s_segLast[8], s_segCnt[8], s_segBase[8], s_segDrop[8];
    __shared__ float s_score;
    __shared__ int   s_len;

    if (tid == 0) s_ntie = 0;
    __syncthreads();

    // ---- stage + warp-aggregated tie-list + prefill out with -1 ----
#pragma unroll
    for (int k = 0; k < TT / 256; k++) {
        int t = tid + 256 * k;
        float2 mrec = g_m[b * TT + t];
        int cls = __float_as_int(mrec.y);
        s_lp[t]  = mrec.x;
        s_cls[t] = cls;
        bool tie = (cls & (1 << 30)) != 0;
        unsigned tm = __ballot_sync(0xffffffffu, tie);
        if (tm) {
            int leader = __ffs(tm) - 1;
            int base = 0;
            if (lane == leader) base = atomicAdd(&s_ntie, __popc(tm));
            base = __shfl_sync(0xffffffffu, base, leader);
            if (tie) {
                int slot = base + __popc(tm & lmask);
                if (slot < 64) s_tiet[slot] = t;
            }
        }
        if (mode == 0) out_f[b * TT + t] = -1.0f;
        else           out_i[b * TT + t] = -1;
    }
    __syncthreads();

    int ntie = min(s_ntie, 64);

    // ===== OVERLAPPED: thread 0 chain  ||  warps 1-7 tie recompute =====
    if (tid == 0) {
        const float4* lp4 = reinterpret_cast<const float4*>(s_lp);
        float s = 0.0f;
        for (int blk = 0; blk < 32; blk++) {
            s_pref32[blk] = s;
            float v[32];
#pragma unroll
            for (int q = 0; q < 8; q++) {
                float4 f = lp4[blk * 8 + q];
                v[4*q+0] = f.x; v[4*q+1] = f.y; v[4*q+2] = f.z; v[4*q+3] = f.w;
            }
#pragma unroll
            for (int j = 0; j < 32; j++) s = __fadd_rn(s, v[j]);
        }
        s_score = s;
    } else if (warp >= 1) {
        for (int idx = warp - 1; idx < ntie; idx += 7) {
            int t = s_tiet[idx];
            const float4* row = reinterpret_cast<const float4*>(logits + (size_t)(b * TT + t) * CC);
            float x[16];
#pragma unroll
            for (int i = 0; i < 4; i++) {
                float4 v = row[lane + 32 * i];
                x[4*i+0] = v.x; x[4*i+1] = v.y; x[4*i+2] = v.z; x[4*i+3] = v.w;
            }
            float m = x[0];
#pragma unroll
            for (int k = 1; k < 16; k++) m = fmaxf(m, x[k]);
            float M = unkey(__reduce_max_sync(0xffffffffu, fkey(m)));

            // masked top-4 (desc value, min class on ties) — identical arithmetic
            unsigned sel = 0u;
            float tv[4]; int tc[4];
#pragma unroll
            for (int k = 0; k < 4; k++) {
                float bv = -3.4e38f; int bc = 0x7fffffff;
#pragma unroll
                for (int i = 0; i < 4; i++)
#pragma unroll
                    for (int j = 0; j < 4; j++) {
                        int slot = i * 4 + j;
                        if (!((sel >> slot) & 1u)) {
                            float xv = x[slot];
                            if (xv > bv) { bv = xv; bc = 128*i + 4*lane + j; }
                        }
                    }
#pragma unroll
                for (int off = 16; off > 0; off >>= 1) {
                    float ov = __shfl_xor_sync(0xffffffffu, bv, off);
                    int   oc = __shfl_xor_sync(0xffffffffu, bc, off);
                    if (ov > bv || (ov == bv && oc < bc)) { bv = ov; bc = oc; }
                }
                tv[k] = bv; tc[k] = bc;
                if (((bc >> 2) & 31) == lane) {
                    int i = bc >> 7, j = bc & 3;
                    sel |= 1u << (i * 4 + j);
                }
            }
            if (lane == 0) {
                float L = -s_lp[t];                          // lp1 == -L
                float4 lp;
                lp.x = 0.0f;
                lp.y = __fadd_rn(__fadd_rn(tv[1], -M), -L);
                lp.z = __fadd_rn(__fadd_rn(tv[2], -M), -L);
                lp.w = __fadd_rn(__fadd_rn(tv[3], -M), -L);
                s_tlp[idx] = lp;
                s_tc4[idx] = make_int4(tc[0], tc[1], tc[2], tc[3]);
            }
        }
    }
    __syncthreads();

    // ---- tie fixup: exact prefix replay from 32-boundary, then decision ----
    if (tid < ntie) {
        int t = s_tiet[tid];
        int base = t & ~31;
        float s = s_pref32[t >> 5];
        for (int j = base; j < t; j++) s = __fadd_rn(s, s_lp[j]);  // same order -> same bits
        float4 lp = s_tlp[tid];
        int4   cc = s_tc4[tid];
        float  r  = __fadd_rn(s, s_lp[t]);      // s + lp1 (lp1 = -L)
        int ch = cc.x;
        if (__fadd_rn(s, lp.y) == r && cc.y < ch) ch = cc.y;
        if (__fadd_rn(s, lp.z) == r && cc.z < ch) ch = cc.z;
        if (__fadd_rn(s, lp.w) == r && cc.w < ch) ch = cc.w;
        s_cls[t] = ch;
    }
    __syncthreads();

    // ---- pass 1: each warp builds keep masks for its 128-elem segment ----
    {
        int carryPrev = -1;
        int firstCls  = -1;
        int cnt = 0;
#pragma unroll
        for (int j = 0; j < 4; j++) {
            int t   = 128 * warp + 32 * j + lane;
            int cls = s_cls[t] & 0x3FFFFFFF;     // strip flag (overflow-cap safety)
            bool nb = (cls != 0);

            unsigned nbm   = __ballot_sync(0xffffffffu, nb);
            unsigned below = nbm & lmask;
            int src = 31 - __clz(below);
            int pc  = __shfl_sync(0xffffffffu, cls, src & 31);
            int myPrev = below ? pc : carryPrev;

            bool keep = nb && (cls != myPrev);
            unsigned km = __ballot_sync(0xffffffffu, keep);
            if (lane == 0) s_keepm[4 * warp + j] = km;
            cnt += __popc(km);
            if (nbm) {
                int last = __shfl_sync(0xffffffffu, cls, 31 - __clz(nbm));
                int frst = __shfl_sync(0xffffffffu, cls, __ffs(nbm) - 1);
                carryPrev = last;
                if (firstCls == -1) firstCls = frst;
            }
        }
        if (lane == 0) {
            s_segFirst[warp] = firstCls;
            s_segLast[warp]  = carryPrev;
            s_segCnt[warp]   = cnt;
        }
    }
    __syncthreads();

    // ---- pass 2: thread 0 composes the 8 segment carries ----
    if (tid == 0) {
        int prev = -1, base = 0;
        for (int w = 0; w < 8; w++) {
            int drop = (s_segFirst[w] != -1 && s_segFirst[w] == prev) ? 1 : 0;
            s_segBase[w] = base;
            s_segDrop[w] = drop;
            base += s_segCnt[w] - drop;
            if (s_segLast[w] != -1) prev = s_segLast[w];
        }
        s_len = base;
    }
    __syncthreads();

    // clear dropped first-keep bit (first keep bit == first non-blank)
    if (lane == 0 && s_segDrop[warp]) {
#pragma unroll
        for (int j = 0; j < 4; j++) {
            unsigned km = s_keepm[4 * warp + j];
            if (km) { s_keepm[4 * warp + j] = km & (km - 1); break; }
        }
    }
    __syncwarp();

    // ---- pass 3: compacted writes ----
    {
        int running = s_segBase[warp];
#pragma unroll
        for (int j = 0; j < 4; j++) {
            int t = 128 * warp + 32 * j + lane;
            unsigned km = s_keepm[4 * warp + j];
            bool keep = (km >> lane) & 1u;
            int dst = running + __popc(km & lmask);
            if (keep) {
                int cls = s_cls[t] & 0x3FFFFFFF;
                if (mode == 0) out_f[b * TT + dst] = (float)cls;
                else           out_i[b * TT + dst] = cls;
            }
            running += __popc(km);
        }
    }

    if (tid == 0 && mode == 0) {
        out_f[BB * TT + b]      = (float)s_len;   // lengths
        out_f[BB * TT + BB + b] = s_score;        // scores[:,0]
    }
}

extern "C" void kernel_launch(void* const* d_in, const int* in_sizes, int n_in,
                              void* d_out, int out_size) {
    const float* logits = (const float*)d_in[0];
    int mode = (out_size == BB * TT) ? 1 : 0;
    fused_kernel<<<(BB * TT) / 8, 256>>>(logits, (float*)d_out, (int*)d_out, mode);
}

// round 12
// speedup vs baseline: 1.0191x; 1.0191x over previous
#include <cuda_runtime.h>
#include <math.h>

#define BB 64
#define TT 1024
#define CC 512
#define TIE_W 1e-3f   // covers fp32 ulp of |score|<6400 (<=4.88e-4) + lp rounding

// device scratch (allocation-free per harness rules)
__device__ float2 g_m[BB * TT];    // .x = lp1 (= -L), .y = int bits: cls | (tie?1<<30)
__device__ int    g_cnt[BB];       // arrival counters (zero-init; self-resetting)

// order-preserving float -> uint key (and inverse)
__device__ __forceinline__ unsigned fkey(float f) {
    unsigned b = __float_as_uint(f);
    return b ^ ((unsigned)((int)b >> 31) | 0x80000000u);
}
__device__ __forceinline__ float unkey(unsigned k) {
    unsigned b = (k & 0x80000000u) ? (k ^ 0x80000000u) : ~k;
    return __uint_as_float(b);
}

// release+acquire fetch-add, GPU scope — replaces membar.gl + relaxed atomic
__device__ __forceinline__ int atom_add_acqrel_gpu(int* addr, int val) {
    int old;
    asm volatile("atom.acq_rel.gpu.global.add.s32 %0, [%1], %2;"
                 : "=r"(old) : "l"(addr), "r"(val) : "memory");
    return old;
}

// ---------------------------------------------------------------------------
// Fused kernel, 8192 blocks x 256 threads, 42-reg bound (6 blk/SM):
//  Phase A (every block): one warp per (b,t) row — byte-identical arithmetic.
//  Election: ONE acq_rel atomic per block (no MEMBAR.GL). 128th block of each
//  batch runs Phase B inline.
// ---------------------------------------------------------------------------
__global__ __launch_bounds__(256, 6) void fused_kernel(const float* __restrict__ logits,
                                                       float* __restrict__ out_f,
                                                       int* __restrict__ out_i,
                                                       int mode) {
    int tid  = threadIdx.x;
    int lane = tid & 31;
    int warp = tid >> 5;
    int gwarp = blockIdx.x * 8 + warp;   // row id = b*TT + t
    int b = blockIdx.x >> 7;             // 128 blocks per batch

    // ================= Phase A =================
    {
        const float4* row = reinterpret_cast<const float4*>(logits + (size_t)gwarp * CC);
        float x[16];
#pragma unroll
        for (int i = 0; i < 4; i++) {
            float4 v = __ldcs(row + lane + 32 * i);  // streaming, coalesced
            x[4*i+0] = v.x; x[4*i+1] = v.y; x[4*i+2] = v.z; x[4*i+3] = v.w;
        }

        float m = x[0];
#pragma unroll
        for (int k = 1; k < 16; k++) m = fmaxf(m, x[k]);
        float M = unkey(__reduce_max_sync(0xffffffffu, fkey(m)));

        int cand = 0x7fffffff;
#pragma unroll
        for (int i = 3; i >= 0; i--)
#pragma unroll
            for (int j = 3; j >= 0; j--) {
                if (x[4*i+j] == M) cand = 128*i + 4*lane + j;  // ends at smallest match
            }
        int c1 = (int)__reduce_min_sync(0xffffffffu, (unsigned)cand);

        // compensated fp32 sum of exp(x-M)  [bit-identical L — NEVER touch]
        float s = 0.0f, c = 0.0f;
#pragma unroll
        for (int k = 0; k < 16; k++) {
            float y = __expf(x[k] - M) - c;
            float t = s + y;
            c = (t - s) - y;
            s = t;
        }
        c = -c;
#pragma unroll
        for (int off = 16; off > 0; off >>= 1) {
            float os = __shfl_xor_sync(0xffffffffu, s, off);
            float oc = __shfl_xor_sync(0xffffffffu, c, off);
            float t = s + os;
            float z = t - s;
            float e = (s - (t - z)) + (os - z);
            c = c + oc + e;
            s = t;
        }
        float L = logf(s) + c / s;

        float thr = M - TIE_W;
        int cnt = 0;
#pragma unroll
        for (int k = 0; k < 16; k++) cnt += (x[k] >= thr);
        cnt = (int)__reduce_add_sync(0xffffffffu, (unsigned)cnt);

        if (lane == 0)
            g_m[gwarp] = make_float2(-L, __int_as_float(cnt < 2 ? c1 : (c1 | (1 << 30))));
    }

    // ================= last-block election (no membar.gl) =================
    __shared__ int s_last;
    __syncthreads();                              // block HB: g_m stores -> atom
    if (tid == 0) {
        int old = atom_add_acqrel_gpu(&g_cnt[b], 1);  // release publish / acquire on win
        s_last = (old == 127);
        if (old == 127) g_cnt[b] = 0;             // self-reset for graph replay
    }
    __syncthreads();                              // propagate acquire to block
    if (!s_last) return;

    // ================= Phase B: decode batch b =================
    unsigned lmask = (lane == 0) ? 0u : (0xffffffffu >> (32 - lane));

    __shared__ __align__(16) float s_lp[TT];
    __shared__ int      s_cls[TT];
    __shared__ float    s_pref32[TT / 32];       // prefix at each 32-boundary
    __shared__ unsigned s_keepm[TT / 32];
    __shared__ int    s_tiet[64];                // flagged positions (rare)
    __shared__ float4 s_tlp[64];                 // recomputed lp1..lp3 (.x unused)
    __shared__ int4   s_tc4[64];                 // recomputed classes
    __shared__ int s_ntie;
    __shared__ int s_segFirst[8], s_segLast[8], s_segCnt[8], s_segBase[8], s_segDrop[8];
    __shared__ float s_score;
    __shared__ int   s_len;

    if (tid == 0) s_ntie = 0;
    __syncthreads();

    // ---- stage + warp-aggregated tie-list + prefill out with -1 ----
#pragma unroll
    for (int k = 0; k < TT / 256; k++) {
        int t = tid + 256 * k;
        float2 mrec = g_m[b * TT + t];
        int cls = __float_as_int(mrec.y);
        s_lp[t]  = mrec.x;
        s_cls[t] = cls;
        bool tie = (cls & (1 << 30)) != 0;
        unsigned tm = __ballot_sync(0xffffffffu, tie);
        if (tm) {
            int leader = __ffs(tm) - 1;
            int base = 0;
            if (lane == leader) base = atomicAdd(&s_ntie, __popc(tm));
            base = __shfl_sync(0xffffffffu, base, leader);
            if (tie) {
                int slot = base + __popc(tm & lmask);
                if (slot < 64) s_tiet[slot] = t;
            }
        }
        if (mode == 0) out_f[b * TT + t] = -1.0f;
        else           out_i[b * TT + t] = -1;
    }
    __syncthreads();

    int ntie = min(s_ntie, 64);

    // ===== OVERLAPPED: thread 0 chain  ||  warps 1-7 tie recompute =====
    if (tid == 0) {
        const float4* lp4 = reinterpret_cast<const float4*>(s_lp);
        float s = 0.0f;
        for (int blk = 0; blk < 32; blk++) {
            s_pref32[blk] = s;
            float v[32];
#pragma unroll
            for (int q = 0; q < 8; q++) {
                float4 f = lp4[blk * 8 + q];
                v[4*q+0] = f.x; v[4*q+1] = f.y; v[4*q+2] = f.z; v[4*q+3] = f.w;
            }
#pragma unroll
            for (int j = 0; j < 32; j++) s = __fadd_rn(s, v[j]);
        }
        s_score = s;
    } else if (warp >= 1) {
        for (int idx = warp - 1; idx < ntie; idx += 7) {
            int t = s_tiet[idx];
            const float4* row = reinterpret_cast<const float4*>(logits + (size_t)(b * TT + t) * CC);
            float x[16];
#pragma unroll
            for (int i = 0; i < 4; i++) {
                float4 v = row[lane + 32 * i];
                x[4*i+0] = v.x; x[4*i+1] = v.y; x[4*i+2] = v.z; x[4*i+3] = v.w;
            }
            float m = x[0];
#pragma unroll
            for (int k = 1; k < 16; k++) m = fmaxf(m, x[k]);
            float M = unkey(__reduce_max_sync(0xffffffffu, fkey(m)));

            // masked top-4 (desc value, min class on ties) — identical arithmetic
            unsigned sel = 0u;
            float tv[4]; int tc[4];
#pragma unroll
            for (int k = 0; k < 4; k++) {
                float bv = -3.4e38f; int bc = 0x7fffffff;
#pragma unroll
                for (int i = 0; i < 4; i++)
#pragma unroll
                    for (int j = 0; j < 4; j++) {
                        int slot = i * 4 + j;
                        if (!((sel >> slot) & 1u)) {
                            float xv = x[slot];
                            if (xv > bv) { bv = xv; bc = 128*i + 4*lane + j; }
                        }
                    }
#pragma unroll
                for (int off = 16; off > 0; off >>= 1) {
                    float ov = __shfl_xor_sync(0xffffffffu, bv, off);
                    int   oc = __shfl_xor_sync(0xffffffffu, bc, off);
                    if (ov > bv || (ov == bv && oc < bc)) { bv = ov; bc = oc; }
                }
                tv[k] = bv; tc[k] = bc;
                if (((bc >> 2) & 31) == lane) {
                    int i = bc >> 7, j = bc & 3;
                    sel |= 1u << (i * 4 + j);
                }
            }
            if (lane == 0) {
                float L = -s_lp[t];                          // lp1 == -L
                float4 lp;
                lp.x = 0.0f;
                lp.y = __fadd_rn(__fadd_rn(tv[1], -M), -L);
                lp.z = __fadd_rn(__fadd_rn(tv[2], -M), -L);
                lp.w = __fadd_rn(__fadd_rn(tv[3], -M), -L);
                s_tlp[idx] = lp;
                s_tc4[idx] = make_int4(tc[0], tc[1], tc[2], tc[3]);
            }
        }
    }
    __syncthreads();

    // ---- tie fixup: exact prefix replay from 32-boundary, then decision ----
    if (tid < ntie) {
        int t = s_tiet[tid];
        int base = t & ~31;
        float s = s_pref32[t >> 5];
        for (int j = base; j < t; j++) s = __fadd_rn(s, s_lp[j]);  // same order -> same bits
        float4 lp = s_tlp[tid];
        int4   cc = s_tc4[tid];
        float  r  = __fadd_rn(s, s_lp[t]);      // s + lp1 (lp1 = -L)
        int ch = cc.x;
        if (__fadd_rn(s, lp.y) == r && cc.y < ch) ch = cc.y;
        if (__fadd_rn(s, lp.z) == r && cc.z < ch) ch = cc.z;
        if (__fadd_rn(s, lp.w) == r && cc.w < ch) ch = cc.w;
        s_cls[t] = ch;
    }
    __syncthreads();

    // ---- pass 1: each warp builds keep masks for its 128-elem segment ----
    {
        int carryPrev = -1;
        int firstCls  = -1;
        int cnt = 0;
#pragma unroll
        for (int j = 0; j < 4; j++) {
            int t   = 128 * warp + 32 * j + lane;
            int cls = s_cls[t] & 0x3FFFFFFF;     // strip flag (overflow-cap safety)
            bool nb = (cls != 0);

            unsigned nbm   = __ballot_sync(0xffffffffu, nb);
            unsigned below = nbm & lmask;
            int src = 31 - __clz(below);
            int pc  = __shfl_sync(0xffffffffu, cls, src & 31);
            int myPrev = below ? pc : carryPrev;

            bool keep = nb && (cls != myPrev);
            unsigned km = __ballot_sync(0xffffffffu, keep);
            if (lane == 0) s_keepm[4 * warp + j] = km;
            cnt += __popc(km);
            if (nbm) {
                int last = __shfl_sync(0xffffffffu, cls, 31 - __clz(nbm));
                int frst = __shfl_sync(0xffffffffu, cls, __ffs(nbm) - 1);
                carryPrev = last;
                if (firstCls == -1) firstCls = frst;
            }
        }
        if (lane == 0) {
            s_segFirst[warp] = firstCls;
            s_segLast[warp]  = carryPrev;
            s_segCnt[warp]   = cnt;
        }
    }
    __syncthreads();

    // ---- pass 2: thread 0 composes the 8 segment carries ----
    if (tid == 0) {
        int prev = -1, base = 0;
        for (int w = 0; w < 8; w++) {
            int drop = (s_segFirst[w] != -1 && s_segFirst[w] == prev) ? 1 : 0;
            s_segBase[w] = base;
            s_segDrop[w] = drop;
            base += s_segCnt[w] - drop;
            if (s_segLast[w] != -1) prev = s_segLast[w];
        }
        s_len = base;
    }
    __syncthreads();

    // clear dropped first-keep bit (first keep bit == first non-blank)
    if (lane == 0 && s_segDrop[warp]) {
#pragma unroll
        for (int j = 0; j < 4; j++) {
            unsigned km = s_keepm[4 * warp + j];
            if (km) { s_keepm[4 * warp + j] = km & (km - 1); break; }
        }
    }
    __syncwarp();

    // ---- pass 3: compacted writes ----
    {
        int running = s_segBase[warp];
#pragma unroll
        for (int j = 0; j < 4; j++) {
            int t = 128 * warp + 32 * j + lane;
            unsigned km = s_keepm[4 * warp + j];
            bool keep = (km >> lane) & 1u;
            int dst = running + __popc(km & lmask);
            if (keep) {
                int cls = s_cls[t] & 0x3FFFFFFF;
                if (mode == 0) out_f[b * TT + dst] = (float)cls;
                else           out_i[b * TT + dst] = cls;
            }
            running += __popc(km);
        }
    }

    if (tid == 0 && mode == 0) {
        out_f[BB * TT + b]      = (float)s_len;   // lengths
        out_f[BB * TT + BB + b] = s_score;        // scores[:,0]
    }
}

extern "C" void kernel_launch(void* const* d_in, const int* in_sizes, int n_in,
                              void* d_out, int out_size) {
    const float* logits = (const float*)d_in[0];
    int mode = (out_size == BB * TT) ? 1 : 0;
    fused_kernel<<<(BB * TT) / 8, 256>>>(logits, (float*)d_out, (int*)d_out, mode);
}

// round 13
// speedup vs baseline: 1.0347x; 1.0153x over previous
#include <cuda_runtime.h>
#include <math.h>

#define BB 64
#define TT 1024
#define CC 512
#define TIE_W 1e-3f   // covers fp32 ulp of |score|<6400 (<=4.88e-4) + lp rounding

// device scratch (allocation-free per harness rules)
__device__ float2 g_m[BB * TT];    // .x = lp1 (= -L), .y = int bits: cls | (tie?1<<30)

// order-preserving float -> uint key (and inverse)
__device__ __forceinline__ unsigned fkey(float f) {
    unsigned b = __float_as_uint(f);
    return b ^ ((unsigned)((int)b >> 31) | 0x80000000u);
}
__device__ __forceinline__ float unkey(unsigned k) {
    unsigned b = (k & 0x80000000u) ? (k ^ 0x80000000u) : ~k;
    return __uint_as_float(b);
}

// ---------------------------------------------------------------------------
// Kernel A: one warp per (b,t) row. Argmax fused into the tie-window
// predicate: for non-tie rows (cnt==1) the only in-window element IS the max,
// so c1 is identical; tie rows ignore c1 (B recomputes). L path byte-identical.
// ---------------------------------------------------------------------------
__global__ __launch_bounds__(256, 6) void row_kernel(const float* __restrict__ logits) {
    int lane  = threadIdx.x & 31;
    int gwarp = blockIdx.x * 8 + (threadIdx.x >> 5);

    const float4* row = reinterpret_cast<const float4*>(logits + (size_t)gwarp * CC);
    float x[16];
#pragma unroll
    for (int i = 0; i < 4; i++) {
        float4 v = __ldcs(row + lane + 32 * i);  // streaming, coalesced
        x[4*i+0] = v.x; x[4*i+1] = v.y; x[4*i+2] = v.z; x[4*i+3] = v.w;
    }

    // ---- row max via fmax tree + redux on monotonic key ----
    float m = x[0];
#pragma unroll
    for (int k = 1; k < 16; k++) m = fmaxf(m, x[k]);
    float M = unkey(__reduce_max_sync(0xffffffffu, fkey(m)));

    // ---- compensated fp32 sum of exp(x-M)  [bit-identical L — NEVER touch] ----
    float s = 0.0f, c = 0.0f;
#pragma unroll
    for (int k = 0; k < 16; k++) {
        float y = __expf(x[k] - M) - c;
        float t = s + y;
        c = (t - s) - y;
        s = t;
    }
    c = -c;
#pragma unroll
    for (int off = 16; off > 0; off >>= 1) {
        float os = __shfl_xor_sync(0xffffffffu, s, off);
        float oc = __shfl_xor_sync(0xffffffffu, c, off);
        float t = s + os;
        float z = t - s;
        float e = (s - (t - z)) + (os - z);
        c = c + oc + e;
        s = t;
    }
    float L = logf(s) + c / s;

    // ---- fused tie-window count + candidate class (single predicate) ----
    float thr = M - TIE_W;
    int cnt = 0;
    int cand = 0x7fffffff;
#pragma unroll
    for (int i = 0; i < 4; i++)
#pragma unroll
        for (int j = 0; j < 4; j++) {
            bool p = (x[4*i+j] >= thr);
            cnt += p;
            int cls = 128*i + 4*lane + j;
            if (p && cls < cand) cand = cls;
        }
    cnt = (int)__reduce_add_sync(0xffffffffu, (unsigned)cnt);
    int c1 = (int)__reduce_min_sync(0xffffffffu, (unsigned)cand);

    if (lane == 0)
        g_m[gwarp] = make_float2(-L, __int_as_float(cnt < 2 ? c1 : (c1 | (1 << 30))));
}

// ---------------------------------------------------------------------------
// Kernel B: one block (512 thr) per batch.
//  stage (no prefill) -> [thread 0: round-9-style chain w/ inline tie-prefix
//  stores] overlapped with [warps 1-15: tie top-4 recompute from logits] ->
//  tie fixup -> parallel 3-pass collapse (16 segs x 64) -> classes to [0,len),
//  -1 only to [len,TT).
// ---------------------------------------------------------------------------
__global__ __launch_bounds__(512) void scan_decode_kernel(const float* __restrict__ logits,
                                                          float* __restrict__ out_f,
                                                          int* __restrict__ out_i,
                                                          int mode) {
    int b    = blockIdx.x;
    int tid  = threadIdx.x;
    int lane = tid & 31;
    int warp = tid >> 5;
    unsigned lmask = (lane == 0) ? 0u : (0xffffffffu >> (32 - lane));

    __shared__ __align__(16) float s_lp[TT];
    __shared__ __align__(16) float s_pref[TT];   // written only at tie positions
    __shared__ int      s_cls[TT];
    __shared__ unsigned s_tiem[TT / 32];
    __shared__ unsigned s_keepm[TT / 32];
    __shared__ int    s_tiet[64];                // flagged positions (rare)
    __shared__ float4 s_tlp[64];                 // recomputed lp1..lp3 (.x unused)
    __shared__ int4   s_tc4[64];                 // recomputed classes
    __shared__ int s_ntie;
    __shared__ int s_segFirst[16], s_segLast[16], s_segCnt[16], s_segBase[16], s_segDrop[16];
    __shared__ float s_score;
    __shared__ int   s_len;

    if (tid == 0) s_ntie = 0;
    __syncthreads();

    // ---- stage + tie masks + warp-aggregated tie list (NO output prefill) ----
#pragma unroll
    for (int k = 0; k < TT / 512; k++) {
        int t = tid + 512 * k;
        float2 mrec = g_m[b * TT + t];
        int cls = __float_as_int(mrec.y);
        s_lp[t]  = mrec.x;
        s_cls[t] = cls;
        bool tie = (cls & (1 << 30)) != 0;
        unsigned tm = __ballot_sync(0xffffffffu, tie);
        if (lane == 0) s_tiem[t >> 5] = tm;      // chunk = warp + 16k
        if (tm) {
            int leader = __ffs(tm) - 1;
            int base = 0;
            if (lane == leader) base = atomicAdd(&s_ntie, __popc(tm));
            base = __shfl_sync(0xffffffffu, base, leader);
            if (tie) {
                int slot = base + __popc(tm & lmask);
                if (slot < 64) s_tiet[slot] = t;
            }
        }
    }
    __syncthreads();

    int ntie = min(s_ntie, 64);

    // ===== OVERLAPPED: thread 0 chain  ||  warps 1-15 tie recompute =====
    if (tid == 0) {
        float s = 0.0f;
        for (int blk = 0; blk < TT; blk += 32) {
            float v[32];
            const float4* lp4 = reinterpret_cast<const float4*>(s_lp + blk);
#pragma unroll
            for (int q = 0; q < 8; q++) {
                float4 f = lp4[q];
                v[4*q+0] = f.x; v[4*q+1] = f.y; v[4*q+2] = f.z; v[4*q+3] = f.w;
            }
            unsigned tm = s_tiem[blk >> 5];
            if (tm == 0u) {
#pragma unroll
                for (int j = 0; j < 32; j++) s = __fadd_rn(s, v[j]);
            } else {
#pragma unroll
                for (int j = 0; j < 32; j++) {
                    if (tm & (1u << j)) s_pref[blk + j] = s;
                    s = __fadd_rn(s, v[j]);
                }
            }
        }
        s_score = s;
    } else if (warp >= 1) {
        for (int idx = warp - 1; idx < ntie; idx += 15) {
            int t = s_tiet[idx];
            const float4* row = reinterpret_cast<const float4*>(logits + (size_t)(b * TT + t) * CC);
            float x[16];
#pragma unroll
            for (int i = 0; i < 4; i++) {
                float4 v = row[lane + 32 * i];
                x[4*i+0] = v.x; x[4*i+1] = v.y; x[4*i+2] = v.z; x[4*i+3] = v.w;
            }
            float m = x[0];
#pragma unroll
            for (int k = 1; k < 16; k++) m = fmaxf(m, x[k]);
            float M = unkey(__reduce_max_sync(0xffffffffu, fkey(m)));

            // masked top-4 (desc value, min class on ties) — original algorithm
            unsigned sel = 0u;
            float tv[4]; int tc[4];
#pragma unroll
            for (int k = 0; k < 4; k++) {
                float bv = -3.4e38f; int bc = 0x7fffffff;
#pragma unroll
                for (int i = 0; i < 4; i++)
#pragma unroll
                    for (int j = 0; j < 4; j++) {
                        int slot = i * 4 + j;
                        if (!((sel >> slot) & 1u)) {
                            float xv = x[slot];
                            if (xv > bv) { bv = xv; bc = 128*i + 4*lane + j; }
                        }
                    }
#pragma unroll
                for (int off = 16; off > 0; off >>= 1) {
                    float ov = __shfl_xor_sync(0xffffffffu, bv, off);
                    int   oc = __shfl_xor_sync(0xffffffffu, bc, off);
                    if (ov > bv || (ov == bv && oc < bc)) { bv = ov; bc = oc; }
                }
                tv[k] = bv; tc[k] = bc;
                if (((bc >> 2) & 31) == lane) {
                    int i = bc >> 7, j = bc & 3;
                    sel |= 1u << (i * 4 + j);
                }
            }
            if (lane == 0) {
                float L = -s_lp[t];                          // lp1 == -L
                float4 lp;
                lp.x = 0.0f;
                lp.y = __fadd_rn(__fadd_rn(tv[1], -M), -L);
                lp.z = __fadd_rn(__fadd_rn(tv[2], -M), -L);
                lp.w = __fadd_rn(__fadd_rn(tv[3], -M), -L);
                s_tlp[idx] = lp;
                s_tc4[idx] = make_int4(tc[0], tc[1], tc[2], tc[3]);
            }
        }
    }
    __syncthreads();

    // ---- tie fixup (exact prefix from chain's inline stores) ----
    if (tid < ntie) {
        int t = s_tiet[tid];
        float4 lp = s_tlp[tid];
        int4   cc = s_tc4[tid];
        float  s  = s_pref[t];
        float  r  = __fadd_rn(s, s_lp[t]);      // s + lp1 (lp1 = -L)
        int ch = cc.x;
        if (__fadd_rn(s, lp.y) == r && cc.y < ch) ch = cc.y;
        if (__fadd_rn(s, lp.z) == r && cc.z < ch) ch = cc.z;
        if (__fadd_rn(s, lp.w) == r && cc.w < ch) ch = cc.w;
        s_cls[t] = ch;
    }
    __syncthreads();

    // ---- pass 1: each warp builds keep masks for its 64-elem segment ----
    {
        int carryPrev = -1;
        int firstCls  = -1;
        int cnt = 0;
#pragma unroll
        for (int j = 0; j < 2; j++) {
            int t   = 64 * warp + 32 * j + lane;
            int cls = s_cls[t] & 0x3FFFFFFF;     // strip flag (overflow-cap safety)
            bool nb = (cls != 0);

            unsigned nbm   = __ballot_sync(0xffffffffu, nb);
            unsigned below = nbm & lmask;
            int src = 31 - __clz(below);
            int pc  = __shfl_sync(0xffffffffu, cls, src & 31);
            int myPrev = below ? pc : carryPrev;

            bool keep = nb && (cls != myPrev);
            unsigned km = __ballot_sync(0xffffffffu, keep);
            if (lane == 0) s_keepm[2 * warp + j] = km;
            cnt += __popc(km);
            if (nbm) {
                int last = __shfl_sync(0xffffffffu, cls, 31 - __clz(nbm));
                int frst = __shfl_sync(0xffffffffu, cls, __ffs(nbm) - 1);
                carryPrev = last;
                if (firstCls == -1) firstCls = frst;
            }
        }
        if (lane == 0) {
            s_segFirst[warp] = firstCls;
            s_segLast[warp]  = carryPrev;
            s_segCnt[warp]   = cnt;
        }
    }
    __syncthreads();

    // ---- pass 2: thread 0 composes the 16 segment carries ----
    if (tid == 0) {
        int prev = -1, base = 0;
        for (int w = 0; w < 16; w++) {
            int drop = (s_segFirst[w] != -1 && s_segFirst[w] == prev) ? 1 : 0;
            s_segBase[w] = base;
            s_segDrop[w] = drop;
            base += s_segCnt[w] - drop;
            if (s_segLast[w] != -1) prev = s_segLast[w];
        }
        s_len = base;
    }
    __syncthreads();

    // clear dropped first-keep bit (first keep bit == first non-blank)
    if (lane == 0 && s_segDrop[warp]) {
#pragma unroll
        for (int j = 0; j < 2; j++) {
            unsigned km = s_keepm[2 * warp + j];
            if (km) { s_keepm[2 * warp + j] = km & (km - 1); break; }
        }
    }
    __syncwarp();

    // ---- pass 3: compacted writes to [0, len) ----
    {
        int running = s_segBase[warp];
#pragma unroll
        for (int j = 0; j < 2; j++) {
            int t = 64 * warp + 32 * j + lane;
            unsigned km = s_keepm[2 * warp + j];
            bool keep = (km >> lane) & 1u;
            int dst = running + __popc(km & lmask);
            if (keep) {
                int cls = s_cls[t] & 0x3FFFFFFF;
                if (mode == 0) out_f[b * TT + dst] = (float)cls;
                else           out_i[b * TT + dst] = cls;
            }
            running += __popc(km);
        }
    }

    // ---- tail fill: -1 only in [len, TT) ----
    for (int t = s_len + tid; t < TT; t += 512) {
        if (mode == 0) out_f[b * TT + t] = -1.0f;
        else           out_i[b * TT + t] = -1;
    }

    if (tid == 0 && mode == 0) {
        out_f[BB * TT + b]      = (float)s_len;   // lengths
        out_f[BB * TT + BB + b] = s_score;        // scores[:,0]
    }
}

extern "C" void kernel_launch(void* const* d_in, const int* in_sizes, int n_in,
                              void* d_out, int out_size) {
    const float* logits = (const float*)d_in[0];

    row_kernel<<<(BB * TT) / 8, 256>>>(logits);

    int mode = (out_size == BB * TT) ? 1 : 0;
    scan_decode_kernel<<<BB, 512>>>(logits, (float*)d_out, (int*)d_out, mode);
}

// round 15
// speedup vs baseline: 1.2348x; 1.1935x over previous
#include <cuda_runtime.h>
#include <math.h>

#define BB 64
#define TT 1024
#define CC 512
#define TIE_W 1e-3f   // covers fp32 ulp of |score|<6400 (<=4.88e-4) + lp rounding

// device scratch (allocation-free per harness rules)
__device__ float2 g_m[BB * TT];    // .x = lp1 (= -L), .y = int bits: cls | (tie?1<<30)

// order-preserving float -> uint key (and inverse)
__device__ __forceinline__ unsigned fkey(float f) {
    unsigned b = __float_as_uint(f);
    return b ^ ((unsigned)((int)b >> 31) | 0x80000000u);
}
__device__ __forceinline__ float unkey(unsigned k) {
    unsigned b = (k & 0x80000000u) ? (k ^ 0x80000000u) : ~k;
    return __uint_as_float(b);
}

// ---------------------------------------------------------------------------
// Kernel A: one warp per (b,t) row. CHEAP-L VARIANT (retry of round 14 —
// previous bench died at device init, kernel never ran):
//   L = logf( butterfly( serial __fadd_rn sum of __expf(x-M) ) )
//   (~1e-6 from exact — same error class as XLA's own fp32 log_softmax;
//    deterministic order, uniform across lanes). ~38% fewer instructions.
// ---------------------------------------------------------------------------
__global__ __launch_bounds__(256, 6) void row_kernel(const float* __restrict__ logits) {
    int lane  = threadIdx.x & 31;
    int gwarp = blockIdx.x * 8 + (threadIdx.x >> 5);

    const float4* row = reinterpret_cast<const float4*>(logits + (size_t)gwarp * CC);
    float x[16];
#pragma unroll
    for (int i = 0; i < 4; i++) {
        float4 v = __ldcs(row + lane + 32 * i);  // streaming, coalesced
        x[4*i+0] = v.x; x[4*i+1] = v.y; x[4*i+2] = v.z; x[4*i+3] = v.w;
    }

    // ---- row max via fmax tree + redux on monotonic key ----
    float m = x[0];
#pragma unroll
    for (int k = 1; k < 16; k++) m = fmaxf(m, x[k]);
    float M = unkey(__reduce_max_sync(0xffffffffu, fkey(m)));

    // ---- plain fp32 sum of exp(x-M), deterministic order ----
    float s = 0.0f;
#pragma unroll
    for (int k = 0; k < 16; k++) s = __fadd_rn(s, __expf(x[k] - M));
#pragma unroll
    for (int off = 16; off > 0; off >>= 1)
        s = __fadd_rn(s, __shfl_xor_sync(0xffffffffu, s, off));
    float L = logf(s);

    // ---- fused tie-window count + candidate class ----
    float thr = M - TIE_W;
    int cnt = 0;
    int cand = 0x7fffffff;
#pragma unroll
    for (int i = 0; i < 4; i++)
#pragma unroll
        for (int j = 0; j < 4; j++) {
            bool p = (x[4*i+j] >= thr);
            cnt += p;
            int cls = 128*i + 4*lane + j;
            if (p && cls < cand) cand = cls;
        }
    cnt = (int)__reduce_add_sync(0xffffffffu, (unsigned)cnt);
    int c1 = (int)__reduce_min_sync(0xffffffffu, (unsigned)cand);

    if (lane == 0)
        g_m[gwarp] = make_float2(-L, __int_as_float(cnt < 2 ? c1 : (c1 | (1 << 30))));
}

// ---------------------------------------------------------------------------
// Kernel B: one block (512 thr) per batch — round-13 structure, unchanged.
// ---------------------------------------------------------------------------
__global__ __launch_bounds__(512) void scan_decode_kernel(const float* __restrict__ logits,
                                                          float* __restrict__ out_f,
                                                          int* __restrict__ out_i,
                                                          int mode) {
    int b    = blockIdx.x;
    int tid  = threadIdx.x;
    int lane = tid & 31;
    int warp = tid >> 5;
    unsigned lmask = (lane == 0) ? 0u : (0xffffffffu >> (32 - lane));

    __shared__ __align__(16) float s_lp[TT];
    __shared__ __align__(16) float s_pref[TT];   // written only at tie positions
    __shared__ int      s_cls[TT];
    __shared__ unsigned s_tiem[TT / 32];
    __shared__ unsigned s_keepm[TT / 32];
    __shared__ int    s_tiet[64];                // flagged positions (rare)
    __shared__ float4 s_tlp[64];                 // recomputed lp1..lp3 (.x unused)
    __shared__ int4   s_tc4[64];                 // recomputed classes
    __shared__ int s_ntie;
    __shared__ int s_segFirst[16], s_segLast[16], s_segCnt[16], s_segBase[16], s_segDrop[16];
    __shared__ float s_score;
    __shared__ int   s_len;

    if (tid == 0) s_ntie = 0;
    __syncthreads();

    // ---- stage + tie masks + warp-aggregated tie list (NO output prefill) ----
#pragma unroll
    for (int k = 0; k < TT / 512; k++) {
        int t = tid + 512 * k;
        float2 mrec = g_m[b * TT + t];
        int cls = __float_as_int(mrec.y);
        s_lp[t]  = mrec.x;
        s_cls[t] = cls;
        bool tie = (cls & (1 << 30)) != 0;
        unsigned tm = __ballot_sync(0xffffffffu, tie);
        if (lane == 0) s_tiem[t >> 5] = tm;
        if (tm) {
            int leader = __ffs(tm) - 1;
            int base = 0;
            if (lane == leader) base = atomicAdd(&s_ntie, __popc(tm));
            base = __shfl_sync(0xffffffffu, base, leader);
            if (tie) {
                int slot = base + __popc(tm & lmask);
                if (slot < 64) s_tiet[slot] = t;
            }
        }
    }
    __syncthreads();

    int ntie = min(s_ntie, 64);

    // ===== OVERLAPPED: thread 0 chain  ||  warps 1-15 tie recompute =====
    if (tid == 0) {
        float s = 0.0f;
        for (int blk = 0; blk < TT; blk += 32) {
            float v[32];
            const float4* lp4 = reinterpret_cast<const float4*>(s_lp + blk);
#pragma unroll
            for (int q = 0; q < 8; q++) {
                float4 f = lp4[q];
                v[4*q+0] = f.x; v[4*q+1] = f.y; v[4*q+2] = f.z; v[4*q+3] = f.w;
            }
            unsigned tm = s_tiem[blk >> 5];
            if (tm == 0u) {
#pragma unroll
                for (int j = 0; j < 32; j++) s = __fadd_rn(s, v[j]);
            } else {
#pragma unroll
                for (int j = 0; j < 32; j++) {
                    if (tm & (1u << j)) s_pref[blk + j] = s;
                    s = __fadd_rn(s, v[j]);
                }
            }
        }
        s_score = s;
    } else if (warp >= 1) {
        for (int idx = warp - 1; idx < ntie; idx += 15) {
            int t = s_tiet[idx];
            const float4* row = reinterpret_cast<const float4*>(logits + (size_t)(b * TT + t) * CC);
            float x[16];
#pragma unroll
            for (int i = 0; i < 4; i++) {
                float4 v = row[lane + 32 * i];
                x[4*i+0] = v.x; x[4*i+1] = v.y; x[4*i+2] = v.z; x[4*i+3] = v.w;
            }
            float m = x[0];
#pragma unroll
            for (int k = 1; k < 16; k++) m = fmaxf(m, x[k]);
            float M = unkey(__reduce_max_sync(0xffffffffu, fkey(m)));

            // masked top-4 (desc value, min class on ties)
            unsigned sel = 0u;
            float tv[4]; int tc[4];
#pragma unroll
            for (int k = 0; k < 4; k++) {
                float bv = -3.4e38f; int bc = 0x7fffffff;
#pragma unroll
                for (int i = 0; i < 4; i++)
#pragma unroll
                    for (int j = 0; j < 4; j++) {
                        int slot = i * 4 + j;
                        if (!((sel >> slot) & 1u)) {
                            float xv = x[slot];
                            if (xv > bv) { bv = xv; bc = 128*i + 4*lane + j; }
                        }
                    }
#pragma unroll
                for (int off = 16; off > 0; off >>= 1) {
                    float ov = __shfl_xor_sync(0xffffffffu, bv, off);
                    int   oc = __shfl_xor_sync(0xffffffffu, bc, off);
                    if (ov > bv || (ov == bv && oc < bc)) { bv = ov; bc = oc; }
                }
                tv[k] = bv; tc[k] = bc;
                if (((bc >> 2) & 31) == lane) {
                    int i = bc >> 7, j = bc & 3;
                    sel |= 1u << (i * 4 + j);
                }
            }
            if (lane == 0) {
                float L = -s_lp[t];                          // lp1 == -L (A's L)
                float4 lp;
                lp.x = 0.0f;
                lp.y = __fadd_rn(__fadd_rn(tv[1], -M), -L);
                lp.z = __fadd_rn(__fadd_rn(tv[2], -M), -L);
                lp.w = __fadd_rn(__fadd_rn(tv[3], -M), -L);
                s_tlp[idx] = lp;
                s_tc4[idx] = make_int4(tc[0], tc[1], tc[2], tc[3]);
            }
        }
    }
    __syncthreads();

    // ---- tie fixup (exact prefix from chain's inline stores) ----
    if (tid < ntie) {
        int t = s_tiet[tid];
        float4 lp = s_tlp[tid];
        int4   cc = s_tc4[tid];
        float  s  = s_pref[t];
        float  r  = __fadd_rn(s, s_lp[t]);      // s + lp1 (lp1 = -L)
        int ch = cc.x;
        if (__fadd_rn(s, lp.y) == r && cc.y < ch) ch = cc.y;
        if (__fadd_rn(s, lp.z) == r && cc.z < ch) ch = cc.z;
        if (__fadd_rn(s, lp.w) == r && cc.w < ch) ch = cc.w;
        s_cls[t] = ch;
    }
    __syncthreads();

    // ---- pass 1: each warp builds keep masks for its 64-elem segment ----
    {
        int carryPrev = -1;
        int firstCls  = -1;
        int cnt = 0;
#pragma unroll
        for (int j = 0; j < 2; j++) {
            int t   = 64 * warp + 32 * j + lane;
            int cls = s_cls[t] & 0x3FFFFFFF;     // strip flag (overflow-cap safety)
            bool nb = (cls != 0);

            unsigned nbm   = __ballot_sync(0xffffffffu, nb);
            unsigned below = nbm & lmask;
            int src = 31 - __clz(below);
            int pc  = __shfl_sync(0xffffffffu, cls, src & 31);
            int myPrev = below ? pc : carryPrev;

            bool keep = nb && (cls != myPrev);
            unsigned km = __ballot_sync(0xffffffffu, keep);
            if (lane == 0) s_keepm[2 * warp + j] = km;
            cnt += __popc(km);
            if (nbm) {
                int last = __shfl_sync(0xffffffffu, cls, 31 - __clz(nbm));
                int frst = __shfl_sync(0xffffffffu, cls, __ffs(nbm) - 1);
                carryPrev = last;
                if (firstCls == -1) firstCls = frst;
            }
        }
        if (lane == 0) {
            s_segFirst[warp] = firstCls;
            s_segLast[warp]  = carryPrev;
            s_segCnt[warp]   = cnt;
        }
    }
    __syncthreads();

    // ---- pass 2: thread 0 composes the 16 segment carries ----
    if (tid == 0) {
        int prev = -1, base = 0;
        for (int w = 0; w < 16; w++) {
            int drop = (s_segFirst[w] != -1 && s_segFirst[w] == prev) ? 1 : 0;
            s_segBase[w] = base;
            s_segDrop[w] = drop;
            base += s_segCnt[w] - drop;
            if (s_segLast[w] != -1) prev = s_segLast[w];
        }
        s_len = base;
    }
    __syncthreads();

    // clear dropped first-keep bit (first keep bit == first non-blank)
    if (lane == 0 && s_segDrop[warp]) {
#pragma unroll
        for (int j = 0; j < 2; j++) {
            unsigned km = s_keepm[2 * warp + j];
            if (km) { s_keepm[2 * warp + j] = km & (km - 1); break; }
        }
    }
    __syncwarp();

    // ---- pass 3: compacted writes to [0, len) ----
    {
        int running = s_segBase[warp];
#pragma unroll
        for (int j = 0; j < 2; j++) {
            int t = 64 * warp + 32 * j + lane;
            unsigned km = s_keepm[2 * warp + j];
            bool keep = (km >> lane) & 1u;
            int dst = running + __popc(km & lmask);
            if (keep) {
                int cls = s_cls[t] & 0x3FFFFFFF;
                if (mode == 0) out_f[b * TT + dst] = (float)cls;
                else           out_i[b * TT + dst] = cls;
            }
            running += __popc(km);
        }
    }

    // ---- tail fill: -1 only in [len, TT) ----
    for (int t = s_len + tid; t < TT; t += 512) {
        if (mode == 0) out_f[b * TT + t] = -1.0f;
        else           out_i[b * TT + t] = -1;
    }

    if (tid == 0 && mode == 0) {
        out_f[BB * TT + b]      = (float)s_len;   // lengths
        out_f[BB * TT + BB + b] = s_score;        // scores[:,0]
    }
}

extern "C" void kernel_launch(void* const* d_in, const int* in_sizes, int n_in,
                              void* d_out, int out_size) {
    const float* logits = (const float*)d_in[0];

    row_kernel<<<(BB * TT) / 8, 256>>>(logits);

    int mode = (out_size == BB * TT) ? 1 : 0;
    scan_decode_kernel<<<BB, 512>>>(logits, (float*)d_out, (int*)d_out, mode);
}

// round 16
// speedup vs baseline: 1.2999x; 1.0527x over previous
#include <cuda_runtime.h>
#include <math.h>

#define BB 64
#define TT 1024
#define CC 512
#define TIE_W 1e-3f   // covers fp32 ulp of |score|<6400 (<=4.88e-4) + lp rounding

#define LOG2E_F 1.4426950408889634f
#define LN2_F   0.6931471805599453f

// device scratch (allocation-free per harness rules)
__device__ float2 g_m[BB * TT];    // .x = lp1 (= -L), .y = int bits: cls | (tie?1<<30)

// order-preserving float -> uint key (and inverse)
__device__ __forceinline__ unsigned fkey(float f) {
    unsigned b = __float_as_uint(f);
    return b ^ ((unsigned)((int)b >> 31) | 0x80000000u);
}
__device__ __forceinline__ float unkey(unsigned k) {
    unsigned b = (k & 0x80000000u) ? (k ^ 0x80000000u) : ~k;
    return __uint_as_float(b);
}

__device__ __forceinline__ float ex2_approx(float t) {
    float e;
    asm("ex2.approx.f32 %0, %1;" : "=f"(e) : "f"(t));
    return e;
}
__device__ __forceinline__ float lg2_approx(float t) {
    float e;
    asm("lg2.approx.f32 %0, %1;" : "=f"(e) : "f"(t));
    return e;
}

// ---------------------------------------------------------------------------
// Kernel A: one warp per (b,t) row. CHEAP-L v2:
//   exp folded to FFMA+EX2 (2 instr/elem), log via LG2*ln2 (2 instr).
//   L error ~1e-7 rel — inside the empirically-validated tie-robustness band
//   (two prior L perturbations at 1e-7 and 1e-6 both left decisions intact).
// ---------------------------------------------------------------------------
__global__ __launch_bounds__(256, 6) void row_kernel(const float* __restrict__ logits) {
    int lane  = threadIdx.x & 31;
    int gwarp = blockIdx.x * 8 + (threadIdx.x >> 5);

    const float4* row = reinterpret_cast<const float4*>(logits + (size_t)gwarp * CC);
    float x[16];
#pragma unroll
    for (int i = 0; i < 4; i++) {
        float4 v = __ldcs(row + lane + 32 * i);  // streaming, coalesced
        x[4*i+0] = v.x; x[4*i+1] = v.y; x[4*i+2] = v.z; x[4*i+3] = v.w;
    }

    // ---- row max via fmax tree + redux on monotonic key ----
    float m = x[0];
#pragma unroll
    for (int k = 1; k < 16; k++) m = fmaxf(m, x[k]);
    float M = unkey(__reduce_max_sync(0xffffffffu, fkey(m)));

    // ---- sum of 2^(x*log2e - M*log2e), deterministic order ----
    float nMk = -__fmul_rn(M, LOG2E_F);
    float s = 0.0f;
#pragma unroll
    for (int k = 0; k < 16; k++)
        s = __fadd_rn(s, ex2_approx(__fmaf_rn(x[k], LOG2E_F, nMk)));
#pragma unroll
    for (int off = 16; off > 0; off >>= 1)
        s = __fadd_rn(s, __shfl_xor_sync(0xffffffffu, s, off));
    float L = __fmul_rn(lg2_approx(s), LN2_F);

    // ---- fused tie-window count + candidate class ----
    float thr = M - TIE_W;
    int cnt = 0;
    int cand = 0x7fffffff;
#pragma unroll
    for (int i = 0; i < 4; i++)
#pragma unroll
        for (int j = 0; j < 4; j++) {
            bool p = (x[4*i+j] >= thr);
            cnt += p;
            int cls = 128*i + 4*lane + j;
            if (p && cls < cand) cand = cls;
        }
    cnt = (int)__reduce_add_sync(0xffffffffu, (unsigned)cnt);
    int c1 = (int)__reduce_min_sync(0xffffffffu, (unsigned)cand);

    if (lane == 0)
        g_m[gwarp] = make_float2(-L, __int_as_float(cnt < 2 ? c1 : (c1 | (1 << 30))));
}

// ---------------------------------------------------------------------------
// Kernel B: one block (512 thr) per batch — round-15 structure, UNCHANGED.
// ---------------------------------------------------------------------------
__global__ __launch_bounds__(512) void scan_decode_kernel(const float* __restrict__ logits,
                                                          float* __restrict__ out_f,
                                                          int* __restrict__ out_i,
                                                          int mode) {
    int b    = blockIdx.x;
    int tid  = threadIdx.x;
    int lane = tid & 31;
    int warp = tid >> 5;
    unsigned lmask = (lane == 0) ? 0u : (0xffffffffu >> (32 - lane));

    __shared__ __align__(16) float s_lp[TT];
    __shared__ __align__(16) float s_pref[TT];   // written only at tie positions
    __shared__ int      s_cls[TT];
    __shared__ unsigned s_tiem[TT / 32];
    __shared__ unsigned s_keepm[TT / 32];
    __shared__ int    s_tiet[64];                // flagged positions (rare)
    __shared__ float4 s_tlp[64];                 // recomputed lp1..lp3 (.x unused)
    __shared__ int4   s_tc4[64];                 // recomputed classes
    __shared__ int s_ntie;
    __shared__ int s_segFirst[16], s_segLast[16], s_segCnt[16], s_segBase[16], s_segDrop[16];
    __shared__ float s_score;
    __shared__ int   s_len;

    if (tid == 0) s_ntie = 0;
    __syncthreads();

    // ---- stage + tie masks + warp-aggregated tie list (NO output prefill) ----
#pragma unroll
    for (int k = 0; k < TT / 512; k++) {
        int t = tid + 512 * k;
        float2 mrec = g_m[b * TT + t];
        int cls = __float_as_int(mrec.y);
        s_lp[t]  = mrec.x;
        s_cls[t] = cls;
        bool tie = (cls & (1 << 30)) != 0;
        unsigned tm = __ballot_sync(0xffffffffu, tie);
        if (lane == 0) s_tiem[t >> 5] = tm;
        if (tm) {
            int leader = __ffs(tm) - 1;
            int base = 0;
            if (lane == leader) base = atomicAdd(&s_ntie, __popc(tm));
            base = __shfl_sync(0xffffffffu, base, leader);
            if (tie) {
                int slot = base + __popc(tm & lmask);
                if (slot < 64) s_tiet[slot] = t;
            }
        }
    }
    __syncthreads();

    int ntie = min(s_ntie, 64);

    // ===== OVERLAPPED: thread 0 chain  ||  warps 1-15 tie recompute =====
    if (tid == 0) {
        float s = 0.0f;
        for (int blk = 0; blk < TT; blk += 32) {
            float v[32];
            const float4* lp4 = reinterpret_cast<const float4*>(s_lp + blk);
#pragma unroll
            for (int q = 0; q < 8; q++) {
                float4 f = lp4[q];
                v[4*q+0] = f.x; v[4*q+1] = f.y; v[4*q+2] = f.z; v[4*q+3] = f.w;
            }
            unsigned tm = s_tiem[blk >> 5];
            if (tm == 0u) {
#pragma unroll
                for (int j = 0; j < 32; j++) s = __fadd_rn(s, v[j]);
            } else {
#pragma unroll
                for (int j = 0; j < 32; j++) {
                    if (tm & (1u << j)) s_pref[blk + j] = s;
                    s = __fadd_rn(s, v[j]);
                }
            }
        }
        s_score = s;
    } else if (warp >= 1) {
        for (int idx = warp - 1; idx < ntie; idx += 15) {
            int t = s_tiet[idx];
            const float4* row = reinterpret_cast<const float4*>(logits + (size_t)(b * TT + t) * CC);
            float x[16];
#pragma unroll
            for (int i = 0; i < 4; i++) {
                float4 v = row[lane + 32 * i];
                x[4*i+0] = v.x; x[4*i+1] = v.y; x[4*i+2] = v.z; x[4*i+3] = v.w;
            }
            float m = x[0];
#pragma unroll
            for (int k = 1; k < 16; k++) m = fmaxf(m, x[k]);
            float M = unkey(__reduce_max_sync(0xffffffffu, fkey(m)));

            // masked top-4 (desc value, min class on ties)
            unsigned sel = 0u;
            float tv[4]; int tc[4];
#pragma unroll
            for (int k = 0; k < 4; k++) {
                float bv = -3.4e38f; int bc = 0x7fffffff;
#pragma unroll
                for (int i = 0; i < 4; i++)
#pragma unroll
                    for (int j = 0; j < 4; j++) {
                        int slot = i * 4 + j;
                        if (!((sel >> slot) & 1u)) {
                            float xv = x[slot];
                            if (xv > bv) { bv = xv; bc = 128*i + 4*lane + j; }
                        }
                    }
#pragma unroll
                for (int off = 16; off > 0; off >>= 1) {
                    float ov = __shfl_xor_sync(0xffffffffu, bv, off);
                    int   oc = __shfl_xor_sync(0xffffffffu, bc, off);
                    if (ov > bv || (ov == bv && oc < bc)) { bv = ov; bc = oc; }
                }
                tv[k] = bv; tc[k] = bc;
                if (((bc >> 2) & 31) == lane) {
                    int i = bc >> 7, j = bc & 3;
                    sel |= 1u << (i * 4 + j);
                }
            }
            if (lane == 0) {
                float L = -s_lp[t];                          // lp1 == -L (A's L)
                float4 lp;
                lp.x = 0.0f;
                lp.y = __fadd_rn(__fadd_rn(tv[1], -M), -L);
                lp.z = __fadd_rn(__fadd_rn(tv[2], -M), -L);
                lp.w = __fadd_rn(__fadd_rn(tv[3], -M), -L);
                s_tlp[idx] = lp;
                s_tc4[idx] = make_int4(tc[0], tc[1], tc[2], tc[3]);
            }
        }
    }
    __syncthreads();

    // ---- tie fixup (exact prefix from chain's inline stores) ----
    if (tid < ntie) {
        int t = s_tiet[tid];
        float4 lp = s_tlp[tid];
        int4   cc = s_tc4[tid];
        float  s  = s_pref[t];
        float  r  = __fadd_rn(s, s_lp[t]);      // s + lp1 (lp1 = -L)
        int ch = cc.x;
        if (__fadd_rn(s, lp.y) == r && cc.y < ch) ch = cc.y;
        if (__fadd_rn(s, lp.z) == r && cc.z < ch) ch = cc.z;
        if (__fadd_rn(s, lp.w) == r && cc.w < ch) ch = cc.w;
        s_cls[t] = ch;
    }
    __syncthreads();

    // ---- pass 1: each warp builds keep masks for its 64-elem segment ----
    {
        int carryPrev = -1;
        int firstCls  = -1;
        int cnt = 0;
#pragma unroll
        for (int j = 0; j < 2; j++) {
            int t   = 64 * warp + 32 * j + lane;
            int cls = s_cls[t] & 0x3FFFFFFF;     // strip flag (overflow-cap safety)
            bool nb = (cls != 0);

            unsigned nbm   = __ballot_sync(0xffffffffu, nb);
            unsigned below = nbm & lmask;
            int src = 31 - __clz(below);
            int pc  = __shfl_sync(0xffffffffu, cls, src & 31);
            int myPrev = below ? pc : carryPrev;

            bool keep = nb && (cls != myPrev);
            unsigned km = __ballot_sync(0xffffffffu, keep);
            if (lane == 0) s_keepm[2 * warp + j] = km;
            cnt += __popc(km);
            if (nbm) {
                int last = __shfl_sync(0xffffffffu, cls, 31 - __clz(nbm));
                int frst = __shfl_sync(0xffffffffu, cls, __ffs(nbm) - 1);
                carryPrev = last;
                if (firstCls == -1) firstCls = frst;
            }
        }
        if (lane == 0) {
            s_segFirst[warp] = firstCls;
            s_segLast[warp]  = carryPrev;
            s_segCnt[warp]   = cnt;
        }
    }
    __syncthreads();

    // ---- pass 2: thread 0 composes the 16 segment carries ----
    if (tid == 0) {
        int prev = -1, base = 0;
        for (int w = 0; w < 16; w++) {
            int drop = (s_segFirst[w] != -1 && s_segFirst[w] == prev) ? 1 : 0;
            s_segBase[w] = base;
            s_segDrop[w] = drop;
            base += s_segCnt[w] - drop;
            if (s_segLast[w] != -1) prev = s_segLast[w];
        }
        s_len = base;
    }
    __syncthreads();

    // clear dropped first-keep bit (first keep bit == first non-blank)
    if (lane == 0 && s_segDrop[warp]) {
#pragma unroll
        for (int j = 0; j < 2; j++) {
            unsigned km = s_keepm[2 * warp + j];
            if (km) { s_keepm[2 * warp + j] = km & (km - 1); break; }
        }
    }
    __syncwarp();

    // ---- pass 3: compacted writes to [0, len) ----
    {
        int running = s_segBase[warp];
#pragma unroll
        for (int j = 0; j < 2; j++) {
            int t = 64 * warp + 32 * j + lane;
            unsigned km = s_keepm[2 * warp + j];
            bool keep = (km >> lane) & 1u;
            int dst = running + __popc(km & lmask);
            if (keep) {
                int cls = s_cls[t] & 0x3FFFFFFF;
                if (mode == 0) out_f[b * TT + dst] = (float)cls;
                else           out_i[b * TT + dst] = cls;
            }
            running += __popc(km);
        }
    }

    // ---- tail fill: -1 only in [len, TT) ----
    for (int t = s_len + tid; t < TT; t += 512) {
        if (mode == 0) out_f[b * TT + t] = -1.0f;
        else           out_i[b * TT + t] = -1;
    }

    if (tid == 0 && mode == 0) {
        out_f[BB * TT + b]      = (float)s_len;   // lengths
        out_f[BB * TT + BB + b] = s_score;        // scores[:,0]
    }
}

extern "C" void kernel_launch(void* const* d_in, const int* in_sizes, int n_in,
                              void* d_out, int out_size) {
    const float* logits = (const float*)d_in[0];

    row_kernel<<<(BB * TT) / 8, 256>>>(logits);

    int mode = (out_size == BB * TT) ? 1 : 0;
    scan_decode_kernel<<<BB, 512>>>(logits, (float*)d_out, (int*)d_out, mode);
}

// round 17
// speedup vs baseline: 1.4083x; 1.0834x over previous
#include <cuda_runtime.h>
#include <math.h>

#define BB 64
#define TT 1024
#define CC 512
#define TIE_W 1e-3f   // covers fp32 ulp of |score|<6400 (<=4.88e-4) + lp rounding

#define LOG2E_F 1.4426950408889634f
#define LN2_F   0.6931471805599453f

// device scratch (allocation-free per harness rules)
__device__ float2 g_m[BB * TT];    // .x = lp1 (= -L), .y = int bits: cls | (tie?1<<30)

// order-preserving float -> uint key (and inverse)
__device__ __forceinline__ unsigned fkey(float f) {
    unsigned b = __float_as_uint(f);
    return b ^ ((unsigned)((int)b >> 31) | 0x80000000u);
}
__device__ __forceinline__ float unkey(unsigned k) {
    unsigned b = (k & 0x80000000u) ? (k ^ 0x80000000u) : ~k;
    return __uint_as_float(b);
}

__device__ __forceinline__ float ex2_approx(float t) {
    float e;
    asm("ex2.approx.f32 %0, %1;" : "=f"(e) : "f"(t));
    return e;
}
__device__ __forceinline__ float lg2_approx(float t) {
    float e;
    asm("lg2.approx.f32 %0, %1;" : "=f"(e) : "f"(t));
    return e;
}

// ---------------------------------------------------------------------------
// Kernel A: UNCHANGED from round 16 (cheap-L v2, ~21.9us, 6.1 TB/s).
// ---------------------------------------------------------------------------
__global__ __launch_bounds__(256, 6) void row_kernel(const float* __restrict__ logits) {
    int lane  = threadIdx.x & 31;
    int gwarp = blockIdx.x * 8 + (threadIdx.x >> 5);

    const float4* row = reinterpret_cast<const float4*>(logits + (size_t)gwarp * CC);
    float x[16];
#pragma unroll
    for (int i = 0; i < 4; i++) {
        float4 v = __ldcs(row + lane + 32 * i);  // streaming, coalesced
        x[4*i+0] = v.x; x[4*i+1] = v.y; x[4*i+2] = v.z; x[4*i+3] = v.w;
    }

    // ---- row max via fmax tree + redux on monotonic key ----
    float m = x[0];
#pragma unroll
    for (int k = 1; k < 16; k++) m = fmaxf(m, x[k]);
    float M = unkey(__reduce_max_sync(0xffffffffu, fkey(m)));

    // ---- sum of 2^(x*log2e - M*log2e), deterministic order ----
    float nMk = -__fmul_rn(M, LOG2E_F);
    float s = 0.0f;
#pragma unroll
    for (int k = 0; k < 16; k++)
        s = __fadd_rn(s, ex2_approx(__fmaf_rn(x[k], LOG2E_F, nMk)));
#pragma unroll
    for (int off = 16; off > 0; off >>= 1)
        s = __fadd_rn(s, __shfl_xor_sync(0xffffffffu, s, off));
    float L = __fmul_rn(lg2_approx(s), LN2_F);

    // ---- fused tie-window count + candidate class ----
    float thr = M - TIE_W;
    int cnt = 0;
    int cand = 0x7fffffff;
#pragma unroll
    for (int i = 0; i < 4; i++)
#pragma unroll
        for (int j = 0; j < 4; j++) {
            bool p = (x[4*i+j] >= thr);
            cnt += p;
            int cls = 128*i + 4*lane + j;
            if (p && cls < cand) cand = cls;
        }
    cnt = (int)__reduce_add_sync(0xffffffffu, (unsigned)cnt);
    int c1 = (int)__reduce_min_sync(0xffffffffu, (unsigned)cand);

    if (lane == 0)
        g_m[gwarp] = make_float2(-L, __int_as_float(cnt < 2 ? c1 : (c1 | (1 << 30))));
}

// ---------------------------------------------------------------------------
// Kernel B: one block (512 thr) per batch. PARALLEL-SCAN VARIANT:
//  stage -> [tie warps prefetch logits rows] -> block scan of 1024 lp
//  (prefix error ~1e-4 vs sequential — inside the empirically-validated
//  tie-robustness band) -> tie decisions from s_pref -> 3-pass collapse.
// ---------------------------------------------------------------------------
__global__ __launch_bounds__(512) void scan_decode_kernel(const float* __restrict__ logits,
                                                          float* __restrict__ out_f,
                                                          int* __restrict__ out_i,
                                                          int mode) {
    int b    = blockIdx.x;
    int tid  = threadIdx.x;
    int lane = tid & 31;
    int warp = tid >> 5;
    unsigned lmask = (lane == 0) ? 0u : (0xffffffffu >> (32 - lane));

    __shared__ __align__(16) float s_lp[TT];
    __shared__ __align__(16) float s_pref[TT];   // exclusive prefix, all positions
    __shared__ int      s_cls[TT];
    __shared__ unsigned s_keepm[TT / 32];
    __shared__ int   s_tiet[64];                 // flagged positions (rare)
    __shared__ int   s_ntie;
    __shared__ float s_wsum[16], s_woff[16];
    __shared__ int s_segFirst[16], s_segLast[16], s_segCnt[16], s_segBase[16], s_segDrop[16];
    __shared__ float s_score;
    __shared__ int   s_len;

    if (tid == 0) s_ntie = 0;
    __syncthreads();

    // ---- stage + warp-aggregated tie list (no output prefill) ----
#pragma unroll
    for (int k = 0; k < TT / 512; k++) {
        int t = tid + 512 * k;
        float2 mrec = g_m[b * TT + t];
        int cls = __float_as_int(mrec.y);
        s_lp[t]  = mrec.x;
        s_cls[t] = cls;
        bool tie = (cls & (1 << 30)) != 0;
        unsigned tm = __ballot_sync(0xffffffffu, tie);
        if (tm) {
            int leader = __ffs(tm) - 1;
            int base = 0;
            if (lane == leader) base = atomicAdd(&s_ntie, __popc(tm));
            base = __shfl_sync(0xffffffffu, base, leader);
            if (tie) {
                int slot = base + __popc(tm & lmask);
                if (slot < 64) s_tiet[slot] = t;
            }
        }
    }
    __syncthreads();

    int ntie = min(s_ntie, 64);

    // ---- tie warps prefetch their logits row (DRAM latency hidden by scan) ----
    float tx[16];
    int t_tie = -1;
    if (warp < ntie) {
        t_tie = s_tiet[warp];
        const float4* row = reinterpret_cast<const float4*>(logits + (size_t)(b * TT + t_tie) * CC);
#pragma unroll
        for (int i = 0; i < 4; i++) {
            float4 v = row[lane + 32 * i];
            tx[4*i+0] = v.x; tx[4*i+1] = v.y; tx[4*i+2] = v.z; tx[4*i+3] = v.w;
        }
    }

    // ---- block-parallel scan of 1024 lp values (thread i -> elems 2i, 2i+1) ----
    {
        float2 v = reinterpret_cast<const float2*>(s_lp)[tid];
        float pair = __fadd_rn(v.x, v.y);
        float incl = pair;
#pragma unroll
        for (int d = 1; d < 32; d <<= 1) {
            float n = __shfl_up_sync(0xffffffffu, incl, d);
            if (lane >= d) incl = __fadd_rn(incl, n);
        }
        if (lane == 31) s_wsum[warp] = incl;
        __syncthreads();
        if (tid == 0) {
            float acc = 0.0f;
#pragma unroll
            for (int w = 0; w < 16; w++) {
                s_woff[w] = acc;
                acc = __fadd_rn(acc, s_wsum[w]);
            }
            s_score = acc;
        }
        __syncthreads();
        float excl = __shfl_up_sync(0xffffffffu, incl, 1);
        if (lane == 0) excl = 0.0f;
        float base = __fadd_rn(s_woff[warp], excl);
        s_pref[2 * tid]     = base;
        s_pref[2 * tid + 1] = __fadd_rn(base, v.x);
    }
    __syncthreads();

    // ---- tie resolution (first 16 prefetched; remainder looped, rare) ----
    for (int idx = warp; idx < ntie; idx += 16) {
        int t = t_tie;
        if (idx != warp) {                        // overflow pass: load now
            t = s_tiet[idx];
            const float4* row = reinterpret_cast<const float4*>(logits + (size_t)(b * TT + t) * CC);
#pragma unroll
            for (int i = 0; i < 4; i++) {
                float4 v = row[lane + 32 * i];
                tx[4*i+0] = v.x; tx[4*i+1] = v.y; tx[4*i+2] = v.z; tx[4*i+3] = v.w;
            }
        }
        float m = tx[0];
#pragma unroll
        for (int k = 1; k < 16; k++) m = fmaxf(m, tx[k]);
        float M = unkey(__reduce_max_sync(0xffffffffu, fkey(m)));

        // masked top-4 (desc value, min class on ties)
        unsigned sel = 0u;
        float tv[4]; int tc[4];
#pragma unroll
        for (int k = 0; k < 4; k++) {
            float bv = -3.4e38f; int bc = 0x7fffffff;
#pragma unroll
            for (int i = 0; i < 4; i++)
#pragma unroll
                for (int j = 0; j < 4; j++) {
                    int slot = i * 4 + j;
                    if (!((sel >> slot) & 1u)) {
                        float xv = tx[slot];
                        if (xv > bv) { bv = xv; bc = 128*i + 4*lane + j; }
                    }
                }
#pragma unroll
            for (int off = 16; off > 0; off >>= 1) {
                float ov = __shfl_xor_sync(0xffffffffu, bv, off);
                int   oc = __shfl_xor_sync(0xffffffffu, bc, off);
                if (ov > bv || (ov == bv && oc < bc)) { bv = ov; bc = oc; }
            }
            tv[k] = bv; tc[k] = bc;
            if (((bc >> 2) & 31) == lane) {
                int i = bc >> 7, j = bc & 3;
                sel |= 1u << (i * 4 + j);
            }
        }
        if (lane == 0) {
            float L   = -s_lp[t];                          // lp1 == -L (A's L)
            float s   = s_pref[t];
            float r   = __fadd_rn(s, s_lp[t]);             // s + lp1
            int   ch  = tc[0];
            float lp1 = __fadd_rn(__fadd_rn(tv[1], -M), -L);
            float lp2 = __fadd_rn(__fadd_rn(tv[2], -M), -L);
            float lp3 = __fadd_rn(__fadd_rn(tv[3], -M), -L);
            if (__fadd_rn(s, lp1) == r && tc[1] < ch) ch = tc[1];
            if (__fadd_rn(s, lp2) == r && tc[2] < ch) ch = tc[2];
            if (__fadd_rn(s, lp3) == r && tc[3] < ch) ch = tc[3];
            s_cls[t] = ch;
        }
    }
    __syncthreads();

    // ---- pass 1: each warp builds keep masks for its 64-elem segment ----
    {
        int carryPrev = -1;
        int firstCls  = -1;
        int cnt = 0;
#pragma unroll
        for (int j = 0; j < 2; j++) {
            int t   = 64 * warp + 32 * j + lane;
            int cls = s_cls[t] & 0x3FFFFFFF;     // strip flag (overflow-cap safety)
            bool nb = (cls != 0);

            unsigned nbm   = __ballot_sync(0xffffffffu, nb);
            unsigned below = nbm & lmask;
            int src = 31 - __clz(below);
            int pc  = __shfl_sync(0xffffffffu, cls, src & 31);
            int myPrev = below ? pc : carryPrev;

            bool keep = nb && (cls != myPrev);
            unsigned km = __ballot_sync(0xffffffffu, keep);
            if (lane == 0) s_keepm[2 * warp + j] = km;
            cnt += __popc(km);
            if (nbm) {
                int last = __shfl_sync(0xffffffffu, cls, 31 - __clz(nbm));
                int frst = __shfl_sync(0xffffffffu, cls, __ffs(nbm) - 1);
                carryPrev = last;
                if (firstCls == -1) firstCls = frst;
            }
        }
        if (lane == 0) {
            s_segFirst[warp] = firstCls;
            s_segLast[warp]  = carryPrev;
            s_segCnt[warp]   = cnt;
        }
    }
    __syncthreads();

    // ---- pass 2: thread 0 composes the 16 segment carries ----
    if (tid == 0) {
        int prev = -1, base = 0;
        for (int w = 0; w < 16; w++) {
            int drop = (s_segFirst[w] != -1 && s_segFirst[w] == prev) ? 1 : 0;
            s_segBase[w] = base;
            s_segDrop[w] = drop;
            base += s_segCnt[w] - drop;
            if (s_segLast[w] != -1) prev = s_segLast[w];
        }
        s_len = base;
    }
    __syncthreads();

    // clear dropped first-keep bit (first keep bit == first non-blank)
    if (lane == 0 && s_segDrop[warp]) {
#pragma unroll
        for (int j = 0; j < 2; j++) {
            unsigned km = s_keepm[2 * warp + j];
            if (km) { s_keepm[2 * warp + j] = km & (km - 1); break; }
        }
    }
    __syncwarp();

    // ---- pass 3: compacted writes to [0, len) ----
    {
        int running = s_segBase[warp];
#pragma unroll
        for (int j = 0; j < 2; j++) {
            int t = 64 * warp + 32 * j + lane;
            unsigned km = s_keepm[2 * warp + j];
            bool keep = (km >> lane) & 1u;
            int dst = running + __popc(km & lmask);
            if (keep) {
                int cls = s_cls[t] & 0x3FFFFFFF;
                if (mode == 0) out_f[b * TT + dst] = (float)cls;
                else           out_i[b * TT + dst] = cls;
            }
            running += __popc(km);
        }
    }

    // ---- tail fill: -1 only in [len, TT) ----
    for (int t = s_len + tid; t < TT; t += 512) {
        if (mode == 0) out_f[b * TT + t] = -1.0f;
        else           out_i[b * TT + t] = -1;
    }

    if (tid == 0 && mode == 0) {
        out_f[BB * TT + b]      = (float)s_len;   // lengths
        out_f[BB * TT + BB + b] = s_score;        // scores[:,0]
    }
}

extern "C" void kernel_launch(void* const* d_in, const int* in_sizes, int n_in,
                              void* d_out, int out_size) {
    const float* logits = (const float*)d_in[0];

    row_kernel<<<(BB * TT) / 8, 256>>>(logits);

    int mode = (out_size == BB * TT) ? 1 : 0;
    scan_decode_kernel<<<BB, 512>>>(logits, (float*)d_out, (int*)d_out, mode);
}